// round 11
// baseline (speedup 1.0000x reference)
#include <cuda_runtime.h>

#define NX 1024
#define NY 1024
#define NB 8
#define CH (NX*NY)
#define NBLOCKS (NY*NB)         // 8192, one row per CTA
#define NPTS 8388608.0

// Physics constants
#define PR     0.71f
#define RA_PR  710.0f
#define HA2_PR 71.0f
#define PR_DA  7.1f
#define DIFF_C 1.6666666666666667f
#define QQ     0.1f
#define DTINV  100.0f

__device__ double   g_partials[NBLOCKS];
__device__ unsigned g_count = 0;   // wraps to 0 on last CTA -> graph-replay safe

// tgrad along x at global index i; W[12] covers x0-4 .. x0+7, center at W[j+4]
__device__ __forceinline__ float d1x(const float* W, int j, int i) {
    if (i == 0)      return W[5] - W[4];
    if (i == NX - 1) return W[j + 4] - W[j + 3];
    return 0.5f * (W[j + 5] - W[j + 3]);
}

// tgrad(tgrad(f,x),x) at index i
__device__ __forceinline__ float d2x(const float* W, int j, int i) {
    if (i == 0)      return 0.5f * W[6] - W[5] + 0.5f * W[4];
    if (i == 1)      return 0.25f * W[7] - 0.75f * W[5] + 0.5f * W[4];
    if (i == NX - 2) return 0.5f * W[j + 5] - 0.75f * W[j + 4] + 0.25f * W[j + 2];
    if (i == NX - 1) return 0.5f * W[j + 4] - W[j + 3] + 0.5f * W[j + 2];
    return 0.25f * (W[j + 6] - 2.0f * W[j + 4] + W[j + 2]);
}

// 12-float x-window: plain predicated float4 loads (NO shuffles — R9 post-mortem)
__device__ __forceinline__ void load_window(const float* __restrict__ row, int tid, int x0, float* W) {
    float4 c = *(const float4*)(row + x0);
    W[4] = c.x; W[5] = c.y; W[6] = c.z; W[7] = c.w;
    if (tid > 0) {
        float4 l = *(const float4*)(row + x0 - 4);
        W[0] = l.x; W[1] = l.y; W[2] = l.z; W[3] = l.w;
    } else { W[0] = W[1] = W[2] = W[3] = 0.0f; }
    if (tid < 255) {
        float4 r = *(const float4*)(row + x0 + 4);
        W[8] = r.x; W[9] = r.y; W[10] = r.z; W[11] = r.w;
    } else { W[8] = W[9] = W[10] = W[11] = 0.0f; }
}

struct Deriv { float v[4], dx[4], dy[4], dxx[4], dyy[4]; };

__device__ __forceinline__ void full_derivs(
    const float* __restrict__ ch, int tid, int y, int x0,
    int rM, int rP, float s1,
    int rA, int rB, float cA, float cC, float cB,
    Deriv& d)
{
    float W[12];
    load_window(ch + (size_t)y * NX, tid, x0, W);
    float4 m  = *(const float4*)(ch + (size_t)rM * NX + x0);
    float4 p  = *(const float4*)(ch + (size_t)rP * NX + x0);
    float4 a  = *(const float4*)(ch + (size_t)rA * NX + x0);
    float4 bb = *(const float4*)(ch + (size_t)rB * NX + x0);
    float mm[4]  = {m.x,  m.y,  m.z,  m.w};
    float pp[4]  = {p.x,  p.y,  p.z,  p.w};
    float aa[4]  = {a.x,  a.y,  a.z,  a.w};
    float bbv[4] = {bb.x, bb.y, bb.z, bb.w};
#pragma unroll
    for (int j = 0; j < 4; j++) {
        int i = x0 + j;
        d.v[j]   = W[j + 4];
        d.dx[j]  = d1x(W, j, i);
        d.dxx[j] = d2x(W, j, i);
        d.dy[j]  = s1 * (pp[j] - mm[j]);
        d.dyy[j] = cA * aa[j] + cC * W[j + 4] + cB * bbv[j];
    }
}

__global__ __launch_bounds__(256)
void physics_loss_kernel(const float* __restrict__ fno, const float* __restrict__ fne,
                         float* __restrict__ out)
{
    const int tid = threadIdx.x;
    const int y   = blockIdx.x;
    const int b   = blockIdx.y;
    const int x0  = tid * 4;

    const int   rM = (y > 0) ? y - 1 : 0;
    const int   rP = (y < NY - 1) ? y + 1 : NY - 1;
    const float s1 = (y == 0 || y == NY - 1) ? 1.0f : 0.5f;

    int rA, rB; float cA, cC, cB;
    if      (y == 0)      { rA = 2;      cA = 0.5f;  cC = 0.5f;   rB = 1;      cB = -1.0f; }
    else if (y == 1)      { rA = 0;      cA = 0.5f;  cC = -0.75f; rB = 3;      cB = 0.25f; }
    else if (y == NY - 2) { rA = NY - 4; cA = 0.25f; cC = -0.75f; rB = NY - 1; cB = 0.5f;  }
    else if (y == NY - 1) { rA = NY - 3; cA = 0.5f;  cC = 0.5f;   rB = NY - 2; cB = -1.0f; }
    else                  { rA = y - 2;  cA = 0.25f; cC = -0.5f;  rB = y + 2;  cB = 0.25f; }

    const size_t base = (size_t)b * 4 * CH;
    const size_t rowo = (size_t)y * NX + x0;

    // f_now fields (U, V, T) — plain loads (match R1 codegen)
    float4 uo4 = *(const float4*)(fno + base + 0 * (size_t)CH + rowo);
    float4 vo4 = *(const float4*)(fno + base + 1 * (size_t)CH + rowo);
    float4 to4 = *(const float4*)(fno + base + 2 * (size_t)CH + rowo);
    float Uo[4] = {uo4.x, uo4.y, uo4.z, uo4.w};
    float Vo[4] = {vo4.x, vo4.y, vo4.z, vo4.w};
    float To[4] = {to4.x, to4.y, to4.z, to4.w};

    float cont[4], resx[4], resy[4], rest[4];

    Deriv D;
    // ---- U_next ----
    full_derivs(fne + base + 0 * (size_t)CH, tid, y, x0, rM, rP, s1, rA, rB, cA, cC, cB, D);
#pragma unroll
    for (int j = 0; j < 4; j++) {
        float Un = D.v[j];
        cont[j] = D.dx[j];
        resx[j] = (Un - Uo[j]) * DTINV + Un * D.dx[j] + Vo[j] * D.dy[j]
                  - PR * (D.dxx[j] + D.dyy[j]) + PR_DA * Un;
    }
    // ---- V_next ----
    full_derivs(fne + base + 1 * (size_t)CH, tid, y, x0, rM, rP, s1, rA, rB, cA, cC, cB, D);
#pragma unroll
    for (int j = 0; j < 4; j++) {
        float Vn = D.v[j];
        cont[j] += D.dy[j];
        resy[j] = (Vn - Vo[j]) * DTINV + Uo[j] * D.dx[j] + Vn * D.dy[j]
                  - PR * (D.dxx[j] + D.dyy[j]) + (HA2_PR + PR_DA) * Vn;
    }
    // ---- T_next ----
    full_derivs(fne + base + 2 * (size_t)CH, tid, y, x0, rM, rP, s1, rA, rB, cA, cC, cB, D);
#pragma unroll
    for (int j = 0; j < 4; j++) {
        float Tn = D.v[j];
        resy[j] -= RA_PR * Tn;
        rest[j] = (Tn - To[j]) * DTINV + Uo[j] * D.dx[j] + Vo[j] * D.dy[j]
                  - DIFF_C * (D.dxx[j] + D.dyy[j]) - QQ * Tn;
    }
    // ---- P_next (dx, dy only) ----
    {
        const float* Pc = fne + base + 3 * (size_t)CH;
        float W[12];
        load_window(Pc + (size_t)y * NX, tid, x0, W);
        float4 m = *(const float4*)(Pc + (size_t)rM * NX + x0);
        float4 p = *(const float4*)(Pc + (size_t)rP * NX + x0);
        float mm[4] = {m.x, m.y, m.z, m.w};
        float pp[4] = {p.x, p.y, p.z, p.w};
#pragma unroll
        for (int j = 0; j < 4; j++) {
            int i = x0 + j;
            resx[j] += d1x(W, j, i);
            resy[j] += s1 * (pp[j] - mm[j]);
        }
    }

    float acc = 0.0f;
#pragma unroll
    for (int j = 0; j < 4; j++) {
        acc += cont[j] * cont[j] + resx[j] * resx[j]
             + resy[j] * resy[j] + rest[j] * rest[j];
    }

    // warp + block reduction
#pragma unroll
    for (int o = 16; o > 0; o >>= 1) acc += __shfl_xor_sync(0xFFFFFFFFu, acc, o);

    __shared__ double ws[8];
    __shared__ bool   is_last;
    if ((tid & 31) == 0) ws[tid >> 5] = (double)acc;
    __syncthreads();

    const int bid = blockIdx.y * NY + blockIdx.x;
    if (tid == 0) {
        double s = 0.0;
#pragma unroll
        for (int k = 0; k < 8; k++) s += ws[k];
        g_partials[bid] = s;
        // RELEASE atomic orders the partial store before the count bump
        // WITHOUT a gpu-scope fence (which would CCTL.IVALL-flush L1 per CTA
        // — the R10 regression).
        unsigned prev;
        asm volatile("atom.release.gpu.global.inc.u32 %0, [%1], %2;"
                     : "=r"(prev)
                     : "l"(&g_count), "r"((unsigned)(NBLOCKS - 1))
                     : "memory");
        is_last = (prev == NBLOCKS - 1);
    }
    __syncthreads();

    // last CTA reduces all partials; __ldcg (L2-only) reads see the released data
    if (is_last) {
        double v = 0.0;
#pragma unroll
        for (int k = 0; k < NBLOCKS / 256; k++)
            v += __ldcg(&g_partials[tid + k * 256]);
#pragma unroll
        for (int o = 16; o > 0; o >>= 1)
            v += __shfl_xor_sync(0xFFFFFFFFu, v, o);
        if ((tid & 31) == 0) ws[tid >> 5] = v;
        __syncthreads();
        if (tid == 0) {
            double s = 0.0;
#pragma unroll
            for (int k = 0; k < 8; k++) s += ws[k];
            double t = s * 1e-4 / NPTS;
            if (t < 1e-10) t = 1e-10;
            if (t > 1.0)   t = 1.0;
            out[0] = (float)t;
        }
    }
}

extern "C" void kernel_launch(void* const* d_in, const int* in_sizes, int n_in,
                              void* d_out, int out_size)
{
    const float* f_now  = (const float*)d_in[0];
    const float* f_next = (const float*)d_in[1];

    dim3 grid(NY, NB);
    physics_loss_kernel<<<grid, 256>>>(f_now, f_next, (float*)d_out);
}

// round 12
// speedup vs baseline: 1.0940x; 1.0940x over previous
#include <cuda_runtime.h>

#define NX 1024
#define NY 1024
#define NB 8
#define CH (NX*NY)
#define NBLOCKS (NY*NB)         // 8192, one row per CTA
#define NPTS 8388608.0

// Physics constants
#define PR     0.71f
#define RA_PR  710.0f
#define HA2_PR 71.0f
#define PR_DA  7.1f
#define DIFF_C 1.6666666666666667f
#define QQ     0.1f
#define DTINV  100.0f

__device__ double g_partials[NBLOCKS];

// tgrad along x at global index i; W[12] covers x0-4 .. x0+7, center at W[j+4]
__device__ __forceinline__ float d1x(const float* W, int j, int i) {
    if (i == 0)      return W[5] - W[4];
    if (i == NX - 1) return W[j + 4] - W[j + 3];
    return 0.5f * (W[j + 5] - W[j + 3]);
}

// tgrad(tgrad(f,x),x) at index i
__device__ __forceinline__ float d2x(const float* W, int j, int i) {
    if (i == 0)      return 0.5f * W[6] - W[5] + 0.5f * W[4];
    if (i == 1)      return 0.25f * W[7] - 0.75f * W[5] + 0.5f * W[4];
    if (i == NX - 2) return 0.5f * W[j + 5] - 0.75f * W[j + 4] + 0.25f * W[j + 2];
    if (i == NX - 1) return 0.5f * W[j + 4] - W[j + 3] + 0.5f * W[j + 2];
    return 0.25f * (W[j + 6] - 2.0f * W[j + 4] + W[j + 2]);
}

// 12-float x-window: plain predicated float4 loads (NO shuffles — R9 post-mortem)
__device__ __forceinline__ void load_window(const float* __restrict__ row, int tid, int x0, float* W) {
    float4 c = *(const float4*)(row + x0);
    W[4] = c.x; W[5] = c.y; W[6] = c.z; W[7] = c.w;
    if (tid > 0) {
        float4 l = *(const float4*)(row + x0 - 4);
        W[0] = l.x; W[1] = l.y; W[2] = l.z; W[3] = l.w;
    } else { W[0] = W[1] = W[2] = W[3] = 0.0f; }
    if (tid < 255) {
        float4 r = *(const float4*)(row + x0 + 4);
        W[8] = r.x; W[9] = r.y; W[10] = r.z; W[11] = r.w;
    } else { W[8] = W[9] = W[10] = W[11] = 0.0f; }
}

struct Deriv { float v[4], dx[4], dy[4], dxx[4], dyy[4]; };

__device__ __forceinline__ void full_derivs(
    const float* __restrict__ ch, int tid, int y, int x0,
    int rM, int rP, float s1,
    int rA, int rB, float cA, float cC, float cB,
    Deriv& d)
{
    float W[12];
    load_window(ch + (size_t)y * NX, tid, x0, W);
    float4 m  = *(const float4*)(ch + (size_t)rM * NX + x0);
    float4 p  = *(const float4*)(ch + (size_t)rP * NX + x0);
    float4 a  = *(const float4*)(ch + (size_t)rA * NX + x0);
    float4 bb = *(const float4*)(ch + (size_t)rB * NX + x0);
    float mm[4]  = {m.x,  m.y,  m.z,  m.w};
    float pp[4]  = {p.x,  p.y,  p.z,  p.w};
    float aa[4]  = {a.x,  a.y,  a.z,  a.w};
    float bbv[4] = {bb.x, bb.y, bb.z, bb.w};
#pragma unroll
    for (int j = 0; j < 4; j++) {
        int i = x0 + j;
        d.v[j]   = W[j + 4];
        d.dx[j]  = d1x(W, j, i);
        d.dxx[j] = d2x(W, j, i);
        d.dy[j]  = s1 * (pp[j] - mm[j]);
        d.dyy[j] = cA * aa[j] + cC * W[j + 4] + cB * bbv[j];
    }
}

__global__ __launch_bounds__(256)
void physics_loss_kernel(const float* __restrict__ fno, const float* __restrict__ fne)
{
    const int tid = threadIdx.x;
    const int y   = blockIdx.x;
    const int b   = blockIdx.y;
    const int x0  = tid * 4;

    const int   rM = (y > 0) ? y - 1 : 0;
    const int   rP = (y < NY - 1) ? y + 1 : NY - 1;
    const float s1 = (y == 0 || y == NY - 1) ? 1.0f : 0.5f;

    int rA, rB; float cA, cC, cB;
    if      (y == 0)      { rA = 2;      cA = 0.5f;  cC = 0.5f;   rB = 1;      cB = -1.0f; }
    else if (y == 1)      { rA = 0;      cA = 0.5f;  cC = -0.75f; rB = 3;      cB = 0.25f; }
    else if (y == NY - 2) { rA = NY - 4; cA = 0.25f; cC = -0.75f; rB = NY - 1; cB = 0.5f;  }
    else if (y == NY - 1) { rA = NY - 3; cA = 0.5f;  cC = 0.5f;   rB = NY - 2; cB = -1.0f; }
    else                  { rA = y - 2;  cA = 0.25f; cC = -0.5f;  rB = y + 2;  cB = 0.25f; }

    const size_t base = (size_t)b * 4 * CH;
    const size_t rowo = (size_t)y * NX + x0;

    // f_now fields (U, V, T)
    float4 uo4 = *(const float4*)(fno + base + 0 * (size_t)CH + rowo);
    float4 vo4 = *(const float4*)(fno + base + 1 * (size_t)CH + rowo);
    float4 to4 = *(const float4*)(fno + base + 2 * (size_t)CH + rowo);
    float Uo[4] = {uo4.x, uo4.y, uo4.z, uo4.w};
    float Vo[4] = {vo4.x, vo4.y, vo4.z, vo4.w};
    float To[4] = {to4.x, to4.y, to4.z, to4.w};

    float cont[4], resx[4], resy[4], rest[4];

    Deriv D;
    // ---- U_next ----
    full_derivs(fne + base + 0 * (size_t)CH, tid, y, x0, rM, rP, s1, rA, rB, cA, cC, cB, D);
#pragma unroll
    for (int j = 0; j < 4; j++) {
        float Un = D.v[j];
        cont[j] = D.dx[j];
        resx[j] = (Un - Uo[j]) * DTINV + Un * D.dx[j] + Vo[j] * D.dy[j]
                  - PR * (D.dxx[j] + D.dyy[j]) + PR_DA * Un;
    }
    // ---- V_next ----
    full_derivs(fne + base + 1 * (size_t)CH, tid, y, x0, rM, rP, s1, rA, rB, cA, cC, cB, D);
#pragma unroll
    for (int j = 0; j < 4; j++) {
        float Vn = D.v[j];
        cont[j] += D.dy[j];
        resy[j] = (Vn - Vo[j]) * DTINV + Uo[j] * D.dx[j] + Vn * D.dy[j]
                  - PR * (D.dxx[j] + D.dyy[j]) + (HA2_PR + PR_DA) * Vn;
    }
    // ---- T_next ----
    full_derivs(fne + base + 2 * (size_t)CH, tid, y, x0, rM, rP, s1, rA, rB, cA, cC, cB, D);
#pragma unroll
    for (int j = 0; j < 4; j++) {
        float Tn = D.v[j];
        resy[j] -= RA_PR * Tn;
        rest[j] = (Tn - To[j]) * DTINV + Uo[j] * D.dx[j] + Vo[j] * D.dy[j]
                  - DIFF_C * (D.dxx[j] + D.dyy[j]) - QQ * Tn;
    }
    // ---- P_next (dx, dy only) ----
    {
        const float* Pc = fne + base + 3 * (size_t)CH;
        float W[12];
        load_window(Pc + (size_t)y * NX, tid, x0, W);
        float4 m = *(const float4*)(Pc + (size_t)rM * NX + x0);
        float4 p = *(const float4*)(Pc + (size_t)rP * NX + x0);
        float mm[4] = {m.x, m.y, m.z, m.w};
        float pp[4] = {p.x, p.y, p.z, p.w};
#pragma unroll
        for (int j = 0; j < 4; j++) {
            int i = x0 + j;
            resx[j] += d1x(W, j, i);
            resy[j] += s1 * (pp[j] - mm[j]);
        }
    }

    float acc = 0.0f;
#pragma unroll
    for (int j = 0; j < 4; j++) {
        acc += cont[j] * cont[j] + resx[j] * resx[j]
             + resy[j] * resy[j] + rest[j] * rest[j];
    }

    // warp + block reduction, then ONE plain store. No atomics, no fences,
    // no last-block branch — keep the hot body's codegen pristine.
#pragma unroll
    for (int o = 16; o > 0; o >>= 1) acc += __shfl_xor_sync(0xFFFFFFFFu, acc, o);

    __shared__ float ws[8];
    if ((tid & 31) == 0) ws[tid >> 5] = acc;
    __syncthreads();
    if (tid == 0) {
        double s = 0.0;
#pragma unroll
        for (int k = 0; k < 8; k++) s += (double)ws[k];
        g_partials[blockIdx.y * NY + blockIdx.x] = s;
    }
}

__global__ __launch_bounds__(1024)
void finalize_kernel(float* __restrict__ out)
{
    const int tid = threadIdx.x;
    double v = 0.0;
#pragma unroll
    for (int k = 0; k < NBLOCKS / 1024; k++)   // 8 loads/thread
        v += g_partials[tid + k * 1024];
#pragma unroll
    for (int o = 16; o > 0; o >>= 1)
        v += __shfl_xor_sync(0xFFFFFFFFu, v, o);
    __shared__ double ws[32];
    if ((tid & 31) == 0) ws[tid >> 5] = v;
    __syncthreads();
    if (tid == 0) {
        double s = 0.0;
#pragma unroll
        for (int k = 0; k < 32; k++) s += ws[k];
        double t = s * 1e-4 / NPTS;
        if (t < 1e-10) t = 1e-10;
        if (t > 1.0)   t = 1.0;
        out[0] = (float)t;
    }
}

extern "C" void kernel_launch(void* const* d_in, const int* in_sizes, int n_in,
                              void* d_out, int out_size)
{
    const float* f_now  = (const float*)d_in[0];
    const float* f_next = (const float*)d_in[1];

    dim3 grid(NY, NB);
    physics_loss_kernel<<<grid, 256>>>(f_now, f_next);
    finalize_kernel<<<1, 1024>>>((float*)d_out);
}